// round 9
// baseline (speedup 1.0000x reference)
#include <cuda_runtime.h>

// BuiltSWAP on qubits A=0, B=7 of a 13-qubit state, batch 64.
// Reference computes state @ M (M = SWAP permutation matrix); after the
// bit-index flip in _swap_matrix this is out[b, j] = state[b, swap_bits(j)]
// with bits 12 and 5 exchanged (SWAP is an involution). The harness output
// buffer is n float32 (complex64 reference coerced to float32 = real part),
// so only state_re is permuted; state_im and M (256 MB) are dead inputs.
//
// The swap mask 0x1020 touches only the low 13 bits, so it applies directly
// to the flat float index g = b*8192 + j (batch bits unaffected):
//   src_global(g) = g ^ (bit12(g) != bit5(g) ? 0x1020 : 0)
//
// Shape ladder (ncu kernel dur): 4096 warps/MLP=1 4.10-4.61us > 2048 warps
// 4.38us > 1024 warps 4.70us -- resident warps monotonically win; the kernel
// is ramp/latency-bound (~1us traffic + launch overhead). Extend the trend:
// 8192 warps (1024 CTAs x 256 threads), one float2 per thread. Swap
// granularity is 32 floats, so a 2-aligned float2 never straddles it.

#define BIT_HI 12
#define BIT_LO 5
#define SWAP_MASK ((1u << BIT_HI) | (1u << BIT_LO))  // 0x1020

#define THREADS 256
#define BLOCKS 1024   // 262144 threads * 2 floats = 524288 floats. Exact.

__device__ __forceinline__ unsigned swap_src_flat(unsigned g) {
    // g is a flat float index; exchange bits 12 and 5 (within the state row).
    unsigned diff = ((g >> BIT_HI) ^ (g >> BIT_LO)) & 1u;
    return g ^ (diff ? SWAP_MASK : 0u);
}

__global__ void __launch_bounds__(THREADS)
swap_gate_real_kernel(const float* __restrict__ state_re,
                      float* __restrict__ out)
{
    const unsigned t = blockIdx.x * THREADS + threadIdx.x;  // float2 index
    const unsigned e = t * 2u;                              // flat float index
    const float2 v = *reinterpret_cast<const float2*>(state_re + swap_src_flat(e));
    *reinterpret_cast<float2*>(out + e) = v;
}

extern "C" void kernel_launch(void* const* d_in, const int* in_sizes, int n_in,
                              void* d_out, int out_size)
{
    const float* state_re = (const float*)d_in[0];
    // d_in[1] = state_im, d_in[2] = M: dead inputs (output is real part only).
    float* out = (float*)d_out;
    swap_gate_real_kernel<<<BLOCKS, THREADS>>>(state_re, out);
}